// round 5
// baseline (speedup 1.0000x reference)
#include <cuda_runtime.h>

// CARAFE: features [2,64,64,256] f32, masks [2,128,128,25] f32, k=5, group=1.
// Nearest 64->128 half-pixel => src = dst >> 1; each source pixel feeds a 2x2
// output block sharing its 5x5 patch.
// R5: SEGW=4 (2048 blocks -> 3 balanced waves instead of 2 with a 38% tail),
//     pure int32 indexing, single base pointer + compile-time immediate
//     offsets for all feature/output accesses.

#define FH 64
#define FW 64
#define C2 128     // 256 channels / 2 (float2 groups)
#define OH 128
#define OW 128
#define KK 25
#define SEGW 4

__device__ __forceinline__ void fma2s(float2& a, const float2 f, const float m) {
    a.x = fmaf(f.x, m, a.x);
    a.y = fmaf(f.y, m, a.y);
}

template<bool CHK>
__device__ __forceinline__ void carafe_body(int seg, int hs, int b,
                                            const float2* __restrict__ F,
                                            float2* __restrict__ O,
                                            const float* __restrict__ smask,
                                            int c2)
{
    const int ws0 = seg * SEGW;
    const float2 z = make_float2(0.f, 0.f);

    // single feature base at (row hs-2, col ws0-2); every access below is an
    // immediate offset (r*FW + j)*C2 float2 = compile-time constant.
    const float2* fb = F + ((b * FH + (hs - 2)) * FW + (ws0 - 2)) * C2 + c2;

    bool rok[5];
    #pragma unroll
    for (int r = 0; r < 5; r++) {
        int hr = hs - 2 + r;
        rok[r] = CHK ? (hr >= 0 && hr < FH) : true;
    }

    // initial 5x5 window: col (ws0-2+j) -> slot j
    float2 w[5][5];
    #pragma unroll
    for (int j = 0; j < 5; j++) {
        bool cok = CHK ? ((ws0 - 2 + j) >= 0 && (ws0 - 2 + j) < FW) : true;
        #pragma unroll
        for (int r = 0; r < 5; r++)
            w[r][j] = (rok[r] && cok) ? fb[(r * FW + j) * C2] : z;
    }

    // single output base at (row 2*hs, col 2*ws0); stores use immediates.
    float2* ob = O + ((b * OH + 2 * hs) * OW + 2 * ws0) * C2 + c2;

    #pragma unroll
    for (int s = 0; s < SEGW; s++) {
        const float4* __restrict__ mp = (const float4*)(smask + s * (KK * 4));

        float2 a0 = z, a1 = z, a2 = z, a3 = z;

        #pragma unroll
        for (int p = 0; p < KK; p++) {
            const int r = p / 5;
            const int d = p % 5;
            const float2 f = w[r][(s + d) % 5];   // compile-time slot
            const float4 m = mp[p];               // LDS.128 broadcast: 4 outputs' masks
            fma2s(a0, f, m.x);
            fma2s(a1, f, m.y);
            fma2s(a2, f, m.z);
            fma2s(a3, f, m.w);
        }

        ob[(2 * s) * C2]                = a0;
        ob[(2 * s + 1) * C2]            = a1;
        ob[(OW + 2 * s) * C2]           = a2;
        ob[(OW + 2 * s + 1) * C2]       = a3;

        if (s < SEGW - 1) {
            // refill col (ws0 + s + 3) into slot s; offset (s+5)*C2 immediate
            const bool cok = CHK ? ((ws0 + s + 3) < FW) : true;
            #pragma unroll
            for (int r = 0; r < 5; r++)
                w[r][s] = (rok[r] && cok) ? fb[(r * FW + (s + 5)) * C2] : z;
        }
    }
}

__global__ __launch_bounds__(128, 6)
void carafe_kernel(const float* __restrict__ features,
                   const float* __restrict__ masks,
                   float* __restrict__ out)
{
    // smask layout: [px(4)][tap(25)][out(4)], out = oy*2+ox; float4-readable per tap
    __shared__ __align__(16) float smask[SEGW * KK * 4];

    const int tid = threadIdx.x;
    const int seg = blockIdx.x;
    const int hs  = blockIdx.y;
    const int b   = blockIdx.z;
    const int ws0 = seg * SEGW;

    // cooperative mask stage: 2 output rows x 8 output cols x 25 taps = 400 floats
    {
        const int mrow0 = ((b * OH + 2 * hs    ) * OW + 2 * ws0) * KK;
        const int mrow1 = ((b * OH + 2 * hs + 1) * OW + 2 * ws0) * KK;
        #pragma unroll
        for (int it = 0; it < 4; it++) {
            int idx = tid + it * 128;
            if (idx < 400) {
                int oy   = idx / 200;
                int j    = idx - oy * 200;     // contiguous in global mask row
                int wrel = j / KK;             // 0..7 output col within segment
                int p    = j - wrel * KK;      // tap
                int px   = wrel >> 1;          // source col in segment
                int ox   = wrel & 1;
                float v = masks[(oy ? mrow1 : mrow0) + j];
                smask[px * (KK * 4) + p * 4 + oy * 2 + ox] = v;
            }
        }
    }
    __syncthreads();

    const float2* F = (const float2*)features;
    float2* O = (float2*)out;

    const bool interior = (seg >= 1) && (seg <= 14) && (hs >= 2) && (hs <= 61);
    if (interior)
        carafe_body<false>(seg, hs, b, F, O, smask, tid);
    else
        carafe_body<true>(seg, hs, b, F, O, smask, tid);
}

extern "C" void kernel_launch(void* const* d_in, const int* in_sizes, int n_in,
                              void* d_out, int out_size) {
    const float* features = (const float*)d_in[0];
    const float* masks    = (const float*)d_in[1];
    float* out            = (float*)d_out;

    dim3 grid(FW / SEGW, FH, 2);   // (16, 64, 2) = 2048 blocks x 4 warps
    carafe_kernel<<<grid, 128>>>(features, masks, out);
}